// round 17
// baseline (speedup 1.0000x reference)
#include <cuda_runtime.h>
#include <cuda_bf16.h>
#include <math.h>
#include <stdint.h>

// ---------------------------------------------------------------------------
// TransformerBlock: B=8192, N=9, DIM=512, HEADS=8, HEAD_DIM=64
// Round 17: depthwise 3x3 merge conv fused into FC2 epilogue via atomicAdd
// (out pre-initialized with b_conv). Everything else frozen from R16.
// ---------------------------------------------------------------------------

#define MROWS (8192 * 9)   // 73728 token rows

typedef __nv_bfloat16  bf16;
typedef __nv_bfloat162 bf162;

// Scratch (allocation-free: static device globals)
__device__ __align__(16) bf16  g_h   [(size_t)MROWS * 512];   // LN out (bf16)
__device__ __align__(16) bf16  g_qkv [(size_t)MROWS * 1536];  // QKV (bf16)
__device__ __align__(16) bf16  g_attn[(size_t)MROWS * 512];   // attn out (bf16)
__device__ __align__(16) float g_x1  [(size_t)MROWS * 512];   // residual after attn (fp32)
__device__ __align__(16) bf16  g_mlp [(size_t)MROWS * 2048];  // GELU(FC1) (bf16)
__device__ __align__(16) bf16  g_wb  [3145728];               // bf16 weights (contiguous)
__device__ __align__(16) float g_bq  [1536];                  // scaled b_qkv (q part x0.125)

__device__ __forceinline__ void cp16s(uint32_t s, const void* src) {
    asm volatile("cp.async.cg.shared.global [%0], [%1], 16;\n" :: "r"(s), "l"(src));
}
__device__ __forceinline__ void cp_commit() { asm volatile("cp.async.commit_group;\n"); }
template <int N> __device__ __forceinline__ void cp_wait() {
    asm volatile("cp.async.wait_group %0;\n" :: "n"(N));
}

__device__ __forceinline__ void mma_bf16(float4& d, const uint32_t a[4], const uint32_t b[2]) {
    asm volatile(
        "mma.sync.aligned.m16n8k16.row.col.f32.bf16.bf16.f32 "
        "{%0,%1,%2,%3}, {%4,%5,%6,%7}, {%8,%9}, {%0,%1,%2,%3};\n"
        : "+f"(d.x), "+f"(d.y), "+f"(d.z), "+f"(d.w)
        : "r"(a[0]), "r"(a[1]), "r"(a[2]), "r"(a[3]), "r"(b[0]), "r"(b[1]));
}
__device__ __forceinline__ void ldsm4(uint32_t& r0, uint32_t& r1, uint32_t& r2,
                                      uint32_t& r3, uint32_t addr) {
    asm volatile("ldmatrix.sync.aligned.m8n8.x4.shared.b16 {%0,%1,%2,%3}, [%4];"
                 : "=r"(r0), "=r"(r1), "=r"(r2), "=r"(r3) : "r"(addr));
}

// swizzled byte offset within one 128x32 bf16 stage-matrix (64B rows)
__device__ __forceinline__ uint32_t swz(int row, int kc) {
    return (uint32_t)(row * 64 + ((kc ^ ((row >> 1) & 3)) << 4));
}

// ---------------------------------------------------------------------------
// Convert all 4 fp32 weight matrices -> bf16 in one launch; q slice of
// w_qkv/b_qkv scaled by 0.125 (power of 2 -> exact).
// ---------------------------------------------------------------------------
__global__ __launch_bounds__(256) void convw4_kernel(
    const float* __restrict__ wq, const float* __restrict__ wp,
    const float* __restrict__ w1, const float* __restrict__ w2,
    const float* __restrict__ bq, bf16* __restrict__ out,
    float* __restrict__ bq_out)
{
    int i = blockIdx.x * 256 + threadIdx.x;   // 0 .. 786431 (float4 index)
    const float4* src;
    int local;
    float sc = 1.0f;
    if (i < 196608)      { src = (const float4*)wq; local = i;
                           if (i < 65536) sc = 0.125f; }
    else if (i < 262144) { src = (const float4*)wp; local = i - 196608; }
    else if (i < 524288) { src = (const float4*)w1; local = i - 262144; }
    else                 { src = (const float4*)w2; local = i - 524288; }
    float4 v = src[local];
    bf162* o = reinterpret_cast<bf162*>(out) + i * 2;
    o[0] = __floats2bfloat162_rn(v.x * sc, v.y * sc);
    o[1] = __floats2bfloat162_rn(v.z * sc, v.w * sc);

    if (i < 384) {   // b_qkv: 1536 floats = 384 float4
        float4 b = reinterpret_cast<const float4*>(bq)[i];
        float bs = (i < 128) ? 0.125f : 1.0f;
        reinterpret_cast<float4*>(bq_out)[i] =
            make_float4(b.x * bs, b.y * bs, b.z * bs, b.w * bs);
    }
}

// ---------------------------------------------------------------------------
// Initialize final output with conv bias: out[b, c] = b_conv[c]
// ---------------------------------------------------------------------------
__global__ __launch_bounds__(256) void initout_kernel(
    const float* __restrict__ bc, float* __restrict__ out)
{
    int i = blockIdx.x * 256 + threadIdx.x;   // over 8192*512
    out[i] = bc[i & 511];
}

// ---------------------------------------------------------------------------
// LayerNorm over last dim (512). One warp per row. fp32 in -> bf16 out.
// ---------------------------------------------------------------------------
__global__ __launch_bounds__(256) void ln_kernel(
    const float* __restrict__ x, const float* __restrict__ gam,
    const float* __restrict__ bet, bf16* __restrict__ out)
{
    int row  = blockIdx.x * 8 + threadIdx.y;
    int lane = threadIdx.x;
    const float4* xr = reinterpret_cast<const float4*>(x) + (size_t)row * 128;
    float4 v[4];
    float s = 0.f, s2 = 0.f;
#pragma unroll
    for (int i = 0; i < 4; i++) {
        v[i] = xr[lane + 32 * i];
        s  += v[i].x + v[i].y + v[i].z + v[i].w;
        s2 += v[i].x * v[i].x + v[i].y * v[i].y + v[i].z * v[i].z + v[i].w * v[i].w;
    }
#pragma unroll
    for (int o = 16; o; o >>= 1) {
        s  += __shfl_xor_sync(0xffffffffu, s,  o);
        s2 += __shfl_xor_sync(0xffffffffu, s2, o);
    }
    float mu   = s * (1.f / 512.f);
    float var  = s2 * (1.f / 512.f) - mu * mu;
    float rstd = rsqrtf(var + 1e-5f);
    bf162* orow = reinterpret_cast<bf162*>(out) + (size_t)row * 256;
    const float4* g4 = reinterpret_cast<const float4*>(gam);
    const float4* b4 = reinterpret_cast<const float4*>(bet);
#pragma unroll
    for (int i = 0; i < 4; i++) {
        int c = lane + 32 * i;
        float4 g = g4[c], b = b4[c];
        float o0 = (v[i].x - mu) * rstd * g.x + b.x;
        float o1 = (v[i].y - mu) * rstd * g.y + b.y;
        float o2 = (v[i].z - mu) * rstd * g.z + b.z;
        float o3 = (v[i].w - mu) * rstd * g.w + b.w;
        orow[2 * c]     = __floats2bfloat162_rn(o0, o1);
        orow[2 * c + 1] = __floats2bfloat162_rn(o2, o3);
    }
}

// ---------------------------------------------------------------------------
// bf16 HMMA GEMM: C[M,N] = A[M,K] @ Bw[N,K]^T + bias[N] (+ epilogue)
//   EP=0: none (bf16 out);  EP=1: exact GELU (bf16 out);  EP=2: +Res (fp32 out)
//   EP=3: +Res, then depthwise-conv scatter into yout via atomicAdd
//         (yout pre-initialized with b_conv); C is not written.
// ---------------------------------------------------------------------------
#define BK     32
#define TILEB  8192                  // bytes per 128x32 bf16 stage-matrix
#define STAGES 6
#define GSMEM  (STAGES * 2 * TILEB)  // 98304 bytes

__device__ __forceinline__ void store2(bf16* C, size_t off, float a, float b) {
    *reinterpret_cast<bf162*>(C + off) = __floats2bfloat162_rn(a, b);
}
__device__ __forceinline__ void store2(float* C, size_t off, float a, float b) {
    *reinterpret_cast<float2*>(C + off) = make_float2(a, b);
}

template <int EP, typename OutT>
__global__ __launch_bounds__(256, 2) void gemm_bf16_kernel(
    const bf16* __restrict__ A, const bf16* __restrict__ Bw,
    const float* __restrict__ bias, const float* __restrict__ Res,
    OutT* __restrict__ C, int N, int K,
    const float* __restrict__ wcv, float* __restrict__ yout)
{
    extern __shared__ char smem[];   // [A stages 0..5][B stages 0..5]
    uint32_t sbase = (uint32_t)__cvta_generic_to_shared(smem);

    int tid  = threadIdx.x;
    int bm   = blockIdx.y * 128, bn = blockIdx.x * 128;
    int warp = tid >> 5, lane = tid & 31;
    int warpM = warp >> 1, warpN = warp & 1;
    int lg = lane >> 2, lt = lane & 3;

    int aRow = warpM * 32 + ((lane >> 3) & 1) * 8 + (lane & 7);
    int aKc  = lane >> 4;
    int bRow = warpN * 64 + (lane >> 4) * 8 + (lane & 7);
    int bKc  = (lane >> 3) & 1;

    int lrow = tid >> 2;
    int lchk = tid & 3;
    const bf16* Ag = A  + (size_t)(bm + lrow) * K + lchk * 8;
    const bf16* Bg = Bw + (size_t)(bn + lrow) * K + lchk * 8;

    float4 acc[2][8];
#pragma unroll
    for (int mt = 0; mt < 2; mt++)
#pragma unroll
        for (int nt = 0; nt < 8; nt++) acc[mt][nt] = make_float4(0.f, 0.f, 0.f, 0.f);

    auto loadTile = [&](int stage, int kt) {
        uint32_t as = sbase + stage * TILEB;
        uint32_t bs = sbase + STAGES * TILEB + stage * TILEB;
#pragma unroll
        for (int p = 0; p < 2; p++) {
            int r = p * 64 + lrow;
            uint32_t off = swz(r, lchk);
            cp16s(as + off, Ag + (size_t)p * 64 * K + kt);
            cp16s(bs + off, Bg + (size_t)p * 64 * K + kt);
        }
        cp_commit();
    };

    auto compute = [&](int stage) {
        uint32_t aBase = sbase + stage * TILEB;
        uint32_t bBase = sbase + STAGES * TILEB + stage * TILEB;
#pragma unroll
        for (int ks = 0; ks < 2; ks++) {
            uint32_t a[2][4], b[8][2];
#pragma unroll
            for (int mt = 0; mt < 2; mt++) {
                int row = aRow + mt * 16;
                ldsm4(a[mt][0], a[mt][1], a[mt][2], a[mt][3],
                      aBase + swz(row, ks * 2 + aKc));
            }
#pragma unroll
            for (int np = 0; np < 4; np++) {
                int row = bRow + np * 16;
                ldsm4(b[2 * np][0], b[2 * np][1], b[2 * np + 1][0], b[2 * np + 1][1],
                      bBase + swz(row, ks * 2 + bKc));
            }
#pragma unroll
            for (int mt = 0; mt < 2; mt++)
#pragma unroll
                for (int nt = 0; nt < 8; nt++)
                    mma_bf16(acc[mt][nt], a[mt], b[nt]);
        }
    };

    int T = K >> 5;

    loadTile(0, 0);
    loadTile(1, BK);
    loadTile(2, 2 * BK);
    loadTile(3, 3 * BK);

    int s0 = 0;
    int sl = 4;
    for (int t0 = 0; t0 < T; t0 += 2) {
        cp_wait<2>();
        __syncthreads();

        compute(s0);
        int s1 = s0 + 1; if (s1 >= STAGES) s1 -= STAGES;
        compute(s1);

        if (t0 + 4 < T) loadTile(sl, (t0 + 4) * BK); else cp_commit();
        int sl2 = sl + 1; if (sl2 >= STAGES) sl2 -= STAGES;
        if (t0 + 5 < T) loadTile(sl2, (t0 + 5) * BK); else cp_commit();

        s0 += 2; if (s0 >= STAGES) s0 -= STAGES;
        sl += 2; if (sl >= STAGES) sl -= STAGES;
    }

    // epilogue
#pragma unroll
    for (int mt = 0; mt < 2; mt++) {
        int row = bm + warpM * 32 + mt * 16 + lg;
#pragma unroll
        for (int nt = 0; nt < 8; nt++) {
            int col = bn + warpN * 64 + nt * 8 + lt * 2;
            float b0 = bias[col], b1 = bias[col + 1];
            float4 v = acc[mt][nt];
            float o00 = v.x + b0, o01 = v.y + b1;
            float o10 = v.z + b0, o11 = v.w + b1;
            if (EP == 3) {
                const float2 r0 = *reinterpret_cast<const float2*>(Res + (size_t)row * N + col);
                const float2 r1 = *reinterpret_cast<const float2*>(Res + (size_t)(row + 8) * N + col);
                o00 += r0.x; o01 += r0.y; o10 += r1.x; o11 += r1.y;
                int rowB = row + 8;
                int wb0 = row / 9,  wn0 = row  - 9 * wb0;
                int wb1 = rowB / 9, wn1 = rowB - 9 * wb1;
                float w00 = wcv[col * 9 + wn0],       w01 = wcv[(col + 1) * 9 + wn0];
                float w10 = wcv[col * 9 + wn1],       w11 = wcv[(col + 1) * 9 + wn1];
                atomicAdd(yout + (size_t)wb0 * 512 + col,     o00 * w00);
                atomicAdd(yout + (size_t)wb0 * 512 + col + 1, o01 * w01);
                atomicAdd(yout + (size_t)wb1 * 512 + col,     o10 * w10);
                atomicAdd(yout + (size_t)wb1 * 512 + col + 1, o11 * w11);
            } else {
                if (EP == 1) {
                    o00 = 0.5f * o00 * (1.f + erff(o00 * 0.70710678f));
                    o01 = 0.5f * o01 * (1.f + erff(o01 * 0.70710678f));
                    o10 = 0.5f * o10 * (1.f + erff(o10 * 0.70710678f));
                    o11 = 0.5f * o11 * (1.f + erff(o11 * 0.70710678f));
                } else if (EP == 2) {
                    const float2 r0 = *reinterpret_cast<const float2*>(Res + (size_t)row * N + col);
                    const float2 r1 = *reinterpret_cast<const float2*>(Res + (size_t)(row + 8) * N + col);
                    o00 += r0.x; o01 += r0.y; o10 += r1.x; o11 += r1.y;
                }
                store2(C, (size_t)row * N + col,       o00, o01);
                store2(C, (size_t)(row + 8) * N + col, o10, o11);
            }
        }
    }
}

// ---------------------------------------------------------------------------
// Window attention (R16, validated). One CTA per window, 8 warps = 8 heads.
// ---------------------------------------------------------------------------
__global__ __launch_bounds__(256) void attn_kernel(
    const bf16* __restrict__ qkv, const float* __restrict__ bias_table,
    bf16* __restrict__ out)
{
    __shared__ __align__(16) bf16 sq[16][520];
    __shared__ __align__(16) bf16 sk[16][520];
    __shared__ __align__(16) bf16 sv[9][520];
    __shared__ float sp[8][81];
    int b   = blockIdx.x;
    int tid = threadIdx.x;
    size_t base = (size_t)b * 9 * 1536;
    uint32_t sqb = (uint32_t)__cvta_generic_to_shared(&sq[0][0]);
    uint32_t skb = (uint32_t)__cvta_generic_to_shared(&sk[0][0]);
    uint32_t svb = (uint32_t)__cvta_generic_to_shared(&sv[0][0]);

    for (int idx = tid; idx < 1728; idx += 256) {
        int n = idx / 192, c = idx - n * 192;
        int mat = c >> 6;
        uint32_t dst = (mat == 0 ? sqb : mat == 1 ? skb : svb)
                     + (uint32_t)(n * 1040 + (c & 63) * 16);
        cp16s(dst, qkv + base + (size_t)n * 1536 + c * 8);
    }
    cp_commit();
    cp_wait<0>();
    __syncthreads();

    int h = tid >> 5, lane = tid & 31;

    // ---- QK^T via HMMA ----
    int aRow = ((lane >> 3) & 1) * 8 + (lane & 7);
    int aK   = (lane >> 4) * 8;
    int bRow = (lane >> 4) * 8 + (lane & 7);
    int bK   = ((lane >> 3) & 1) * 8;

    float4 s0 = make_float4(0.f, 0.f, 0.f, 0.f);
    float4 s1 = make_float4(0.f, 0.f, 0.f, 0.f);
#pragma unroll
    for (int c = 0; c < 4; c++) {
        uint32_t a[4], bb[4];
        uint32_t aAddr = sqb + (uint32_t)(aRow * 1040 + (h * 64 + c * 16 + aK) * 2);
        uint32_t bAddr = skb + (uint32_t)(bRow * 1040 + (h * 64 + c * 16 + bK) * 2);
        ldsm4(a[0], a[1], a[2], a[3], aAddr);
        ldsm4(bb[0], bb[1], bb[2], bb[3], bAddr);
        uint32_t b0[2] = { bb[0], bb[1] };
        uint32_t b1[2] = { bb[2], bb[3] };
        mma_bf16(s0, a, b0);
        mma_bf16(s1, a, b1);
    }

    {
        int row = lane >> 2;
        int col = (lane & 3) * 2;
        sp[h][row * 9 + col]     = s0.x;
        sp[h][row * 9 + col + 1] = s0.y;
        if (row == 0) {
            sp[h][8 * 9 + col]     = s0.z;
            sp[h][8 * 9 + col + 1] = s0.w;
        }
        if ((lane & 3) == 0) {
            sp[h][row * 9 + 8] = s1.x;
            if (row == 0) sp[h][8 * 9 + 8] = s1.z;
        }
    }
    __syncwarp();

    if (lane < 9) {
        int n = lane;
        int ndiv = n / 3, nmod = n - 3 * ndiv;
        float sc[9];
#pragma unroll
        for (int m = 0; m < 9; m++) {
            int mdiv = m / 3, mmod = m - 3 * mdiv;
            int di = ndiv - mdiv + 2;
            int dj = nmod - mmod + 2;
            sc[m] = sp[h][n * 9 + m] + bias_table[(di * 5 + dj) * 8 + h];
        }
        float mx = -1e30f;
#pragma unroll
        for (int m = 0; m < 9; m++) mx = fmaxf(mx, sc[m]);
        float e[9], sum = 0.f;
#pragma unroll
        for (int m = 0; m < 9; m++) { e[m] = __expf(sc[m] - mx); sum += e[m]; }
        float inv = 1.f / sum;
#pragma unroll
        for (int m = 0; m < 9; m++) sp[h][n * 9 + m] = e[m] * inv;
    }
    __syncwarp();

    float a0[9], a1[9];
#pragma unroll
    for (int n = 0; n < 9; n++) { a0[n] = 0.f; a1[n] = 0.f; }
#pragma unroll
    for (int m = 0; m < 9; m++) {
        float2 vf = __bfloat1622float2(
            *reinterpret_cast<const bf162*>(&sv[m][h * 64 + 2 * lane]));
#pragma unroll
        for (int n = 0; n < 9; n++) {
            float p = sp[h][n * 9 + m];
            a0[n] = fmaf(p, vf.x, a0[n]);
            a1[n] = fmaf(p, vf.y, a1[n]);
        }
    }
#pragma unroll
    for (int n = 0; n < 9; n++) {
        size_t o = ((size_t)b * 9 + n) * 512 + h * 64;
        *reinterpret_cast<bf162*>(out + o + 2 * lane) =
            __floats2bfloat162_rn(a0[n], a1[n]);
    }
}

// ---------------------------------------------------------------------------
extern "C" void kernel_launch(void* const* d_in, const int* in_sizes, int n_in,
                              void* d_out, int out_size)
{
    const float* x          = (const float*)d_in[0];
    const float* gamma1     = (const float*)d_in[1];
    const float* beta1      = (const float*)d_in[2];
    const float* w_qkv      = (const float*)d_in[3];
    const float* b_qkv      = (const float*)d_in[4];
    const float* bias_table = (const float*)d_in[5];
    const float* w_proj     = (const float*)d_in[6];
    const float* b_proj     = (const float*)d_in[7];
    const float* gamma2     = (const float*)d_in[8];
    const float* beta2      = (const float*)d_in[9];
    const float* w_fc1      = (const float*)d_in[10];
    const float* b_fc1      = (const float*)d_in[11];
    const float* w_fc2      = (const float*)d_in[12];
    const float* b_fc2      = (const float*)d_in[13];
    const float* w_conv     = (const float*)d_in[14];
    const float* b_conv     = (const float*)d_in[15];
    float* out = (float*)d_out;

    bf16 *h, *qkv, *attn, *mlp, *wb;
    float *x1, *bqs;
    cudaGetSymbolAddress((void**)&h,    g_h);
    cudaGetSymbolAddress((void**)&qkv,  g_qkv);
    cudaGetSymbolAddress((void**)&attn, g_attn);
    cudaGetSymbolAddress((void**)&x1,   g_x1);
    cudaGetSymbolAddress((void**)&mlp,  g_mlp);
    cudaGetSymbolAddress((void**)&wb,   g_wb);
    cudaGetSymbolAddress((void**)&bqs,  g_bq);

    cudaFuncSetAttribute(gemm_bf16_kernel<0, bf16>,
                         cudaFuncAttributeMaxDynamicSharedMemorySize, GSMEM);
    cudaFuncSetAttribute(gemm_bf16_kernel<1, bf16>,
                         cudaFuncAttributeMaxDynamicSharedMemorySize, GSMEM);
    cudaFuncSetAttribute(gemm_bf16_kernel<2, float>,
                         cudaFuncAttributeMaxDynamicSharedMemorySize, GSMEM);
    cudaFuncSetAttribute(gemm_bf16_kernel<3, float>,
                         cudaFuncAttributeMaxDynamicSharedMemorySize, GSMEM);

    bf16* wq = wb;
    bf16* wp = wb + 786432;
    bf16* w1 = wb + 1048576;
    bf16* w2 = wb + 2097152;

    // weight conversions + q-scale folding
    convw4_kernel<<<3072, 256>>>(w_qkv, w_proj, w_fc1, w_fc2, b_qkv, wb, bqs);
    // out = b_conv broadcast (conv accumulates into it via atomics)
    initout_kernel<<<(8192 * 512) / 256, 256>>>(b_conv, out);

    const int MB = MROWS / 128;   // 576 row tiles

    // LN1: x -> h (bf16)
    ln_kernel<<<MROWS / 8, dim3(32, 8)>>>(x, gamma1, beta1, h);
    // QKV (q pre-scaled): h @ wq^T + bqs -> qkv (bf16)
    gemm_bf16_kernel<0, bf16><<<dim3(12, MB), 256, GSMEM>>>(
        h, wq, bqs, nullptr, qkv, 1536, 512, nullptr, nullptr);
    // window attention -> attn (bf16)
    attn_kernel<<<8192, 256>>>(qkv, bias_table, attn);
    // proj + shortcut: attn @ wp^T + b_proj + x -> x1 (fp32)
    gemm_bf16_kernel<2, float><<<dim3(4, MB), 256, GSMEM>>>(
        attn, wp, b_proj, x, x1, 512, 512, nullptr, nullptr);
    // LN2: x1 -> h (bf16)
    ln_kernel<<<MROWS / 8, dim3(32, 8)>>>(x1, gamma2, beta2, h);
    // FC1 + GELU: h @ w1^T + b_fc1 -> mlp (bf16)
    gemm_bf16_kernel<1, bf16><<<dim3(16, MB), 256, GSMEM>>>(
        h, w1, b_fc1, nullptr, mlp, 2048, 512, nullptr, nullptr);
    // FC2 + residual + fused depthwise conv scatter -> out
    gemm_bf16_kernel<3, float><<<dim3(4, MB), 256, GSMEM>>>(
        mlp, w2, b_fc2, x1, (float*)nullptr, 512, 2048, w_conv, out);
}